// round 1
// baseline (speedup 1.0000x reference)
#include <cuda_runtime.h>
#include <math.h>

// Problem constants (fixed shapes per reference)
#define D    128
#define CIN  384
#define TM   64     // edges per block (edge kernel)
#define TK   32     // K chunk
#define GN   16     // nodes per block (GRU kernel)

#define N_MAX 20000

// Scratch: aggregated messages per node (segment_sum result)
__device__ float g_recv[(size_t)N_MAX * D];

// ---------------------------------------------------------------------------
__global__ void zero_recv_kernel(int n4) {
    int i = blockIdx.x * blockDim.x + threadIdx.x;
    if (i < n4) ((float4*)g_recv)[i] = make_float4(0.f, 0.f, 0.f, 0.f);
}

// ---------------------------------------------------------------------------
// Edge MLP: messages[e,:] = relu(concat(nodes[snd], nodes[rcv], edges[e]) @ W + b)
// Fused: gather + GEMM + bias + relu + store messages + atomic segment-sum.
// Block: 256 threads computing a [64 x 128] output tile, K looped in 12x32.
__global__ __launch_bounds__(256) void edge_kernel(
    const float* __restrict__ nodes, const float* __restrict__ edges,
    const float* __restrict__ W, const float* __restrict__ bvec,
    const int* __restrict__ snd, const int* __restrict__ rcv,
    float* __restrict__ msg_out, int E_)
{
    __shared__ float sA[TK][TM + 1];   // [k][row], padded: conflict-free
    __shared__ float sB[TK * D];       // [k][col], linear
    __shared__ int   sSnd[TM], sRcv[TM];

    const int t  = threadIdx.x;
    const int e0 = blockIdx.x * TM;

    if (t < TM)            sSnd[t]      = snd[min(e0 + t, E_ - 1)];
    else if (t < 2 * TM)   sRcv[t - TM] = rcv[min(e0 + t - TM, E_ - 1)];
    __syncthreads();

    const int tx = t & 31;   // col group: cols tx*4 .. tx*4+3
    const int ty = t >> 5;   // row group: rows ty*8 .. ty*8+7

    float c[8][4];
    #pragma unroll
    for (int i = 0; i < 8; ++i)
        #pragma unroll
        for (int j = 0; j < 4; ++j) c[i][j] = 0.f;

    const int lane  = t & 31;   // k index within chunk for loads
    const int rbase = t >> 5;   // warp id -> 8 rows

    for (int kt = 0; kt < CIN / TK; ++kt) {
        // ---- load A tile (gathered concat), 8 rows per warp, k = lane ----
        #pragma unroll
        for (int i = 0; i < 8; ++i) {
            int row = rbase * 8 + i;
            int e   = min(e0 + row, E_ - 1);
            float v;
            if (kt < 4) {
                v = nodes[(size_t)sSnd[row] * D + kt * TK + lane];
            } else if (kt < 8) {
                v = nodes[(size_t)sRcv[row] * D + (kt - 4) * TK + lane];
            } else {
                v = edges[(size_t)e * D + (kt - 8) * TK + lane];
            }
            sA[lane][row] = v;
        }
        // ---- load B tile (W rows kt*32..+31), fully linear, vectorized ----
        {
            const float4* W4 = (const float4*)(W + (size_t)kt * TK * D);
            float4* sB4 = (float4*)sB;
            #pragma unroll
            for (int i = 0; i < 4; ++i) sB4[t + i * 256] = W4[t + i * 256];
        }
        __syncthreads();

        #pragma unroll
        for (int kk = 0; kk < TK; ++kk) {
            float a[8];
            #pragma unroll
            for (int i = 0; i < 8; ++i) a[i] = sA[kk][ty * 8 + i];
            float4 bv = *(const float4*)&sB[kk * D + tx * 4];
            #pragma unroll
            for (int i = 0; i < 8; ++i) {
                c[i][0] = fmaf(a[i], bv.x, c[i][0]);
                c[i][1] = fmaf(a[i], bv.y, c[i][1]);
                c[i][2] = fmaf(a[i], bv.z, c[i][2]);
                c[i][3] = fmaf(a[i], bv.w, c[i][3]);
            }
        }
        __syncthreads();
    }

    float4 bias = *(const float4*)&bvec[tx * 4];
    #pragma unroll
    for (int i = 0; i < 8; ++i) {
        int row = ty * 8 + i;
        int e   = e0 + row;
        if (e >= E_) break;
        float4 m;
        m.x = fmaxf(c[i][0] + bias.x, 0.f);
        m.y = fmaxf(c[i][1] + bias.y, 0.f);
        m.z = fmaxf(c[i][2] + bias.z, 0.f);
        m.w = fmaxf(c[i][3] + bias.w, 0.f);
        *(float4*)&msg_out[(size_t)e * D + tx * 4] = m;
        float* rp = &g_recv[(size_t)sRcv[row] * D + tx * 4];
        atomicAdd(rp + 0, m.x);
        atomicAdd(rp + 1, m.y);
        atomicAdd(rp + 2, m.z);
        atomicAdd(rp + 3, m.w);
    }
}

// ---------------------------------------------------------------------------
// GRU cell. Per output element j (node n):
//   s_r = recv@Wi[:,j]     + nodes@Wh[:,j]       (+ bi[j])
//   s_z = recv@Wi[:,128+j] + nodes@Wh[:,128+j]   (+ bi[128+j])
//   i_n = recv@Wi[:,256+j] (+ bi[256+j]);  h_n = nodes@Wh[:,256+j]
//   r = sig(s_r); z = sig(s_z); n = tanh(i_n + r*(h_n + bh_n[j]))
//   out = (1-z)*n + z*nodes[n,j]
// Block: 256 threads, 16 nodes x 128 cols; each thread: 2 rows x 4 cols.
__global__ __launch_bounds__(256) void gru_kernel(
    const float* __restrict__ nodes, const float* __restrict__ Wi,
    const float* __restrict__ bi, const float* __restrict__ Wh,
    const float* __restrict__ bhn, float* __restrict__ out, int N_)
{
    __shared__ float sR[GN][D];
    __shared__ float sH[GN][D];

    const int t  = threadIdx.x;
    const int n0 = blockIdx.x * GN;

    #pragma unroll
    for (int i = 0; i < (GN * D) / 256; ++i) {
        int idx = t + i * 256;
        int r = idx >> 7, cc = idx & 127;
        int node = min(n0 + r, N_ - 1);
        sR[r][cc] = g_recv[(size_t)node * D + cc];
        sH[r][cc] = nodes[(size_t)node * D + cc];
    }
    __syncthreads();

    const int tx = t & 31;       // cols tx*4..+3
    const int ty = t >> 5;       // rows ty*2, ty*2+1
    const int r0 = ty * 2, r1 = ty * 2 + 1;
    const int col = tx * 4;

    float aR[2][4], aZ[2][4], aIN[2][4], aHN[2][4];
    #pragma unroll
    for (int i = 0; i < 2; ++i)
        #pragma unroll
        for (int j = 0; j < 4; ++j) { aR[i][j]=0.f; aZ[i][j]=0.f; aIN[i][j]=0.f; aHN[i][j]=0.f; }

    // Pass 1: recv @ Wi  (accumulate r, z, i_n)
    #pragma unroll 4
    for (int k = 0; k < D; ++k) {
        float4 wr = *(const float4*)&Wi[(size_t)k * 3 * D + col];
        float4 wz = *(const float4*)&Wi[(size_t)k * 3 * D + D + col];
        float4 wn = *(const float4*)&Wi[(size_t)k * 3 * D + 2 * D + col];
        float a0 = sR[r0][k], a1 = sR[r1][k];
        aR[0][0]=fmaf(a0,wr.x,aR[0][0]); aR[0][1]=fmaf(a0,wr.y,aR[0][1]); aR[0][2]=fmaf(a0,wr.z,aR[0][2]); aR[0][3]=fmaf(a0,wr.w,aR[0][3]);
        aR[1][0]=fmaf(a1,wr.x,aR[1][0]); aR[1][1]=fmaf(a1,wr.y,aR[1][1]); aR[1][2]=fmaf(a1,wr.z,aR[1][2]); aR[1][3]=fmaf(a1,wr.w,aR[1][3]);
        aZ[0][0]=fmaf(a0,wz.x,aZ[0][0]); aZ[0][1]=fmaf(a0,wz.y,aZ[0][1]); aZ[0][2]=fmaf(a0,wz.z,aZ[0][2]); aZ[0][3]=fmaf(a0,wz.w,aZ[0][3]);
        aZ[1][0]=fmaf(a1,wz.x,aZ[1][0]); aZ[1][1]=fmaf(a1,wz.y,aZ[1][1]); aZ[1][2]=fmaf(a1,wz.z,aZ[1][2]); aZ[1][3]=fmaf(a1,wz.w,aZ[1][3]);
        aIN[0][0]=fmaf(a0,wn.x,aIN[0][0]); aIN[0][1]=fmaf(a0,wn.y,aIN[0][1]); aIN[0][2]=fmaf(a0,wn.z,aIN[0][2]); aIN[0][3]=fmaf(a0,wn.w,aIN[0][3]);
        aIN[1][0]=fmaf(a1,wn.x,aIN[1][0]); aIN[1][1]=fmaf(a1,wn.y,aIN[1][1]); aIN[1][2]=fmaf(a1,wn.z,aIN[1][2]); aIN[1][3]=fmaf(a1,wn.w,aIN[1][3]);
    }
    // Pass 2: nodes @ Wh  (accumulate r, z, h_n)
    #pragma unroll 4
    for (int k = 0; k < D; ++k) {
        float4 wr = *(const float4*)&Wh[(size_t)k * 3 * D + col];
        float4 wz = *(const float4*)&Wh[(size_t)k * 3 * D + D + col];
        float4 wn = *(const float4*)&Wh[(size_t)k * 3 * D + 2 * D + col];
        float a0 = sH[r0][k], a1 = sH[r1][k];
        aR[0][0]=fmaf(a0,wr.x,aR[0][0]); aR[0][1]=fmaf(a0,wr.y,aR[0][1]); aR[0][2]=fmaf(a0,wr.z,aR[0][2]); aR[0][3]=fmaf(a0,wr.w,aR[0][3]);
        aR[1][0]=fmaf(a1,wr.x,aR[1][0]); aR[1][1]=fmaf(a1,wr.y,aR[1][1]); aR[1][2]=fmaf(a1,wr.z,aR[1][2]); aR[1][3]=fmaf(a1,wr.w,aR[1][3]);
        aZ[0][0]=fmaf(a0,wz.x,aZ[0][0]); aZ[0][1]=fmaf(a0,wz.y,aZ[0][1]); aZ[0][2]=fmaf(a0,wz.z,aZ[0][2]); aZ[0][3]=fmaf(a0,wz.w,aZ[0][3]);
        aZ[1][0]=fmaf(a1,wz.x,aZ[1][0]); aZ[1][1]=fmaf(a1,wz.y,aZ[1][1]); aZ[1][2]=fmaf(a1,wz.z,aZ[1][2]); aZ[1][3]=fmaf(a1,wz.w,aZ[1][3]);
        aHN[0][0]=fmaf(a0,wn.x,aHN[0][0]); aHN[0][1]=fmaf(a0,wn.y,aHN[0][1]); aHN[0][2]=fmaf(a0,wn.z,aHN[0][2]); aHN[0][3]=fmaf(a0,wn.w,aHN[0][3]);
        aHN[1][0]=fmaf(a1,wn.x,aHN[1][0]); aHN[1][1]=fmaf(a1,wn.y,aHN[1][1]); aHN[1][2]=fmaf(a1,wn.z,aHN[1][2]); aHN[1][3]=fmaf(a1,wn.w,aHN[1][3]);
    }

    float4 br = *(const float4*)&bi[col];
    float4 bz = *(const float4*)&bi[D + col];
    float4 bn = *(const float4*)&bi[2 * D + col];
    float4 bh = *(const float4*)&bhn[col];
    const float brv[4] = {br.x, br.y, br.z, br.w};
    const float bzv[4] = {bz.x, bz.y, bz.z, bz.w};
    const float bnv[4] = {bn.x, bn.y, bn.z, bn.w};
    const float bhv[4] = {bh.x, bh.y, bh.z, bh.w};

    #pragma unroll
    for (int rr = 0; rr < 2; ++rr) {
        int r = ty * 2 + rr;
        int node = n0 + r;
        if (node >= N_) break;
        float o[4];
        #pragma unroll
        for (int j = 0; j < 4; ++j) {
            float rg = 1.f / (1.f + expf(-(aR[rr][j] + brv[j])));
            float zg = 1.f / (1.f + expf(-(aZ[rr][j] + bzv[j])));
            float ng = tanhf(aIN[rr][j] + bnv[j] + rg * (aHN[rr][j] + bhv[j]));
            float h  = sH[r][col + j];
            o[j] = (1.f - zg) * ng + zg * h;
        }
        *(float4*)&out[(size_t)node * D + col] = make_float4(o[0], o[1], o[2], o[3]);
    }
}

// ---------------------------------------------------------------------------
extern "C" void kernel_launch(void* const* d_in, const int* in_sizes, int n_in,
                              void* d_out, int out_size)
{
    const float* nodes  = (const float*)d_in[0];
    const float* edges  = (const float*)d_in[1];
    const float* W_edge = (const float*)d_in[2];
    const float* b_edge = (const float*)d_in[3];
    const float* Wi     = (const float*)d_in[4];
    const float* bi     = (const float*)d_in[5];
    const float* Wh     = (const float*)d_in[6];
    const float* bh_n   = (const float*)d_in[7];
    const int*   snd    = (const int*)d_in[8];
    const int*   rcv    = (const int*)d_in[9];

    const int N_ = in_sizes[0] / D;
    const int E_ = in_sizes[8];

    float* new_nodes = (float*)d_out;                       // [N, D]
    float* messages  = (float*)d_out + (size_t)N_ * D;      // [E, D]

    // 1) zero the segment-sum accumulator
    int n4 = (N_ * D) / 4;
    zero_recv_kernel<<<(n4 + 255) / 256, 256>>>(n4);

    // 2) edge MLP + messages + atomic aggregation
    edge_kernel<<<(E_ + TM - 1) / TM, 256>>>(nodes, edges, W_edge, b_edge,
                                             snd, rcv, messages, E_);

    // 3) GRU update
    gru_kernel<<<(N_ + GN - 1) / GN, 256>>>(nodes, Wi, bi, Wh, bh_n,
                                            new_nodes, N_);
}

// round 3
// speedup vs baseline: 1.7369x; 1.7369x over previous
#include <cuda_runtime.h>
#include <cuda_bf16.h>
#include <cstdint>
#include <math.h>

#define D      128
#define N_MAX  20000
#define E_MAX  640000

// ---------------- device scratch (no allocs allowed) ----------------
__device__ float g_recv[(size_t)N_MAX * D];
// W_edge pre-split into bf16 hi/lo, stored in mma fragment order:
// index ((c*8 + s)*16 + j)*32 + lane  -> uint2 {b0, b1}
__device__ uint2 g_Bh[3 * 8 * 16 * 32];
__device__ uint2 g_Bl[3 * 8 * 16 * 32];
__device__ int   g_count[N_MAX];
__device__ int   g_off[N_MAX + 1];
__device__ int   g_cursor[N_MAX];
__device__ int   g_elist[E_MAX];

__device__ __forceinline__ uint32_t pack_bf2(float a, float b) {
    __nv_bfloat162 h = __floats2bfloat162_rn(a, b);   // .x = a (low 16), .y = b
    return *(uint32_t*)&h;
}

#define MMA_BF16(d, a0, a1, a2, a3, b0, b1)                                    \
    asm volatile("mma.sync.aligned.m16n8k16.row.col.f32.bf16.bf16.f32 "        \
                 "{%0,%1,%2,%3}, {%4,%5,%6,%7}, {%8,%9}, {%0,%1,%2,%3};"       \
                 : "+f"((d)[0]), "+f"((d)[1]), "+f"((d)[2]), "+f"((d)[3])      \
                 : "r"(a0), "r"(a1), "r"(a2), "r"(a3), "r"(b0), "r"(b1))

// ---------------------------------------------------------------------------
// Prep: zero histogram; split W_edge (bf16 hi/lo) into mma-fragment order.
__global__ void prep_kernel(const float* __restrict__ W, int N_) {
    const int stride = gridDim.x * blockDim.x;
    const int TOT = 3 * 8 * 16 * 32;
    for (int i = blockIdx.x * blockDim.x + threadIdx.x; i < TOT; i += stride) {
        int l = i & 31, j = (i >> 5) & 15, s = (i >> 9) & 7, c = i >> 12;
        int k = c * 128 + s * 16 + (l & 3) * 2;
        int n = j * 8 + (l >> 2);
        float w00 = W[(size_t)(k + 0) * D + n];
        float w01 = W[(size_t)(k + 1) * D + n];
        float w10 = W[(size_t)(k + 8) * D + n];
        float w11 = W[(size_t)(k + 9) * D + n];
        float h00 = __bfloat162float(__float2bfloat16_rn(w00));
        float h01 = __bfloat162float(__float2bfloat16_rn(w01));
        float h10 = __bfloat162float(__float2bfloat16_rn(w10));
        float h11 = __bfloat162float(__float2bfloat16_rn(w11));
        g_Bh[i] = make_uint2(pack_bf2(h00, h01), pack_bf2(h10, h11));
        g_Bl[i] = make_uint2(pack_bf2(w00 - h00, w01 - h01),
                             pack_bf2(w10 - h10, w11 - h11));
    }
    for (int i = blockIdx.x * blockDim.x + threadIdx.x; i < N_; i += stride)
        g_count[i] = 0;
}

__global__ void hist_kernel(const int* __restrict__ rcv, int E_) {
    int i = blockIdx.x * blockDim.x + threadIdx.x;
    if (i < E_) atomicAdd(&g_count[rcv[i]], 1);
}

__global__ void scan_kernel(int N_, int E_) {
    __shared__ int part[1024];
    const int t = threadIdx.x;
    const int chunk = (N_ + 1023) >> 10;
    const int lo = t * chunk, hi = min(N_, lo + chunk);
    int s = 0;
    for (int i = lo; i < hi; ++i) s += g_count[i];
    part[t] = s;
    __syncthreads();
    if (t == 0) {
        int run = 0;
        for (int i = 0; i < 1024; ++i) { int v = part[i]; part[i] = run; run += v; }
    }
    __syncthreads();
    int run = part[t];
    for (int i = lo; i < hi; ++i) {
        g_off[i] = run; g_cursor[i] = run;
        run += g_count[i];
    }
    if (t == 0) g_off[N_] = E_;
}

__global__ void scatter_kernel(const int* __restrict__ rcv, int E_) {
    int i = blockIdx.x * blockDim.x + threadIdx.x;
    if (i < E_) {
        int p = atomicAdd(&g_cursor[rcv[i]], 1);
        g_elist[p] = i;
    }
}

// ---------------------------------------------------------------------------
// Edge GEMM via mma.sync bf16 (3x split).
// CTA: 512 threads = 16 warps. Tile: 256 edges x 128 cols, K=384 in 3 chunks.
// SMEM: B frags hi [0,32K) lo [32K,64K); A hi [64K, +69632), A lo after.
#define A_PITCH 272            // bytes per A row (128 bf16 = 256B + 16B pad)
#define SM_BH   0
#define SM_BL   32768
#define SM_AH   65536
#define SM_AL   (65536 + 256 * A_PITCH)
#define SM_EDGE_TOTAL (65536 + 2 * 256 * A_PITCH)

__global__ __launch_bounds__(512, 1) void edge_mma_kernel(
    const float* __restrict__ nodes, const float* __restrict__ edges,
    const float* __restrict__ bvec, const int* __restrict__ snd,
    const int* __restrict__ rcv, float* __restrict__ msg, int E_)
{
    extern __shared__ __align__(16) char sm[];
    __shared__ float s_bias[128];

    const int t    = threadIdx.x;
    const int warp = t >> 5, lane = t & 31;
    const int e0   = blockIdx.x * 256;

    if (t < 128) s_bias[t] = bvec[t];

    // gather coordinates: thread -> (row, 64-col half)
    const int row = t >> 1, hf = t & 1;
    const int eg = min(e0 + row, E_ - 1);
    const float* __restrict__ pS = nodes + (size_t)__ldg(&snd[eg]) * D;
    const float* __restrict__ pR = nodes + (size_t)__ldg(&rcv[eg]) * D;
    const float* __restrict__ pE = edges + (size_t)eg * D;

    float acc[16][4];
    #pragma unroll
    for (int j = 0; j < 16; ++j)
        #pragma unroll
        for (int q = 0; q < 4; ++q) acc[j][q] = 0.f;

    const int rA   = warp * 16 + (lane >> 2);          // A fragment row (first)
    char* aHip = sm + SM_AH + rA * A_PITCH + (lane & 3) * 4;
    char* aLop = sm + SM_AL + rA * A_PITCH + (lane & 3) * 4;
    char* bHip = sm + SM_BH + lane * 8;
    char* bLop = sm + SM_BL + lane * 8;

    char* awh = sm + SM_AH + row * A_PITCH + hf * 128;
    char* awl = sm + SM_AL + row * A_PITCH + hf * 128;

    for (int c = 0; c < 3; ++c) {
        if (c) __syncthreads();
        // ---- stage A: gather 64 floats/thread, split hi/lo bf16, store ----
        const float* src = (c == 0 ? pS : (c == 1 ? pR : pE)) + hf * 64;
        #pragma unroll
        for (int q = 0; q < 8; ++q) {
            float4 v0 = __ldg((const float4*)(src + q * 8));
            float4 v1 = __ldg((const float4*)(src + q * 8 + 4));
            float h0 = __bfloat162float(__float2bfloat16_rn(v0.x));
            float h1 = __bfloat162float(__float2bfloat16_rn(v0.y));
            float h2 = __bfloat162float(__float2bfloat16_rn(v0.z));
            float h3 = __bfloat162float(__float2bfloat16_rn(v0.w));
            float h4 = __bfloat162float(__float2bfloat16_rn(v1.x));
            float h5 = __bfloat162float(__float2bfloat16_rn(v1.y));
            float h6 = __bfloat162float(__float2bfloat16_rn(v1.z));
            float h7 = __bfloat162float(__float2bfloat16_rn(v1.w));
            uint4 hv = make_uint4(pack_bf2(h0, h1), pack_bf2(h2, h3),
                                  pack_bf2(h4, h5), pack_bf2(h6, h7));
            uint4 lv = make_uint4(pack_bf2(v0.x - h0, v0.y - h1),
                                  pack_bf2(v0.z - h2, v0.w - h3),
                                  pack_bf2(v1.x - h4, v1.y - h5),
                                  pack_bf2(v1.z - h6, v1.w - h7));
            *(uint4*)(awh + q * 16) = hv;
            *(uint4*)(awl + q * 16) = lv;
        }
        // ---- stage B: linear copy of fragment-ordered chunk (32KB x2) ----
        {
            const uint4* gbh = (const uint4*)g_Bh + (size_t)c * 2048;
            const uint4* gbl = (const uint4*)g_Bl + (size_t)c * 2048;
            #pragma unroll
            for (int q = 0; q < 4; ++q) {
                int i = t + q * 512;
                *(uint4*)(sm + SM_BH + i * 16) = __ldg(&gbh[i]);
                *(uint4*)(sm + SM_BL + i * 16) = __ldg(&gbl[i]);
            }
        }
        __syncthreads();

        // ---- compute: 8 k-steps x 16 n-tiles x 3 mma ----
        #pragma unroll
        for (int s = 0; s < 8; ++s) {
            uint32_t ah0 = *(const uint32_t*)(aHip + s * 32);
            uint32_t ah1 = *(const uint32_t*)(aHip + s * 32 + 8 * A_PITCH);
            uint32_t ah2 = *(const uint32_t*)(aHip + s * 32 + 16);
            uint32_t ah3 = *(const uint32_t*)(aHip + s * 32 + 8 * A_PITCH + 16);
            uint32_t al0 = *(const uint32_t*)(aLop + s * 32);
            uint32_t al1 = *(const uint32_t*)(aLop + s * 32 + 8 * A_PITCH);
            uint32_t al2 = *(const uint32_t*)(aLop + s * 32 + 16);
            uint32_t al3 = *(const uint32_t*)(aLop + s * 32 + 8 * A_PITCH + 16);
            #pragma unroll
            for (int j = 0; j < 16; ++j) {
                uint2 bh = *(const uint2*)(bHip + s * 4096 + j * 256);
                uint2 bl = *(const uint2*)(bLop + s * 4096 + j * 256);
                MMA_BF16(acc[j], ah0, ah1, ah2, ah3, bh.x, bh.y);
                MMA_BF16(acc[j], ah0, ah1, ah2, ah3, bl.x, bl.y);
                MMA_BF16(acc[j], al0, al1, al2, al3, bh.x, bh.y);
            }
        }
    }

    // ---- epilogue: bias + relu -> messages ----
    const int er0 = e0 + warp * 16 + (lane >> 2);
    const int er1 = er0 + 8;
    const int cb  = (lane & 3) * 2;
    #pragma unroll
    for (int j = 0; j < 16; ++j) {
        int col = j * 8 + cb;
        float b0 = s_bias[col], b1 = s_bias[col + 1];
        if (er0 < E_) {
            float2 o;
            o.x = fmaxf(acc[j][0] + b0, 0.f);
            o.y = fmaxf(acc[j][1] + b1, 0.f);
            *(float2*)(msg + (size_t)er0 * D + col) = o;
        }
        if (er1 < E_) {
            float2 o;
            o.x = fmaxf(acc[j][2] + b0, 0.f);
            o.y = fmaxf(acc[j][3] + b1, 0.f);
            *(float2*)(msg + (size_t)er1 * D + col) = o;
        }
    }
}

// ---------------------------------------------------------------------------
// CSR gather-reduce: g_recv[n,:] = sum_{edges e with rcv==n} messages[e,:]
__global__ __launch_bounds__(128) void aggregate_kernel(const float* __restrict__ msg, int N_) {
    const int n = blockIdx.x;
    const int t = threadIdx.x;
    const int s = g_off[n], e = g_off[n + 1];
    float a0 = 0.f, a1 = 0.f;
    int i = s;
    for (; i + 2 <= e; i += 2) {
        int i0 = __ldg(&g_elist[i]);
        int i1 = __ldg(&g_elist[i + 1]);
        a0 += __ldg(&msg[(size_t)i0 * D + t]);
        a1 += __ldg(&msg[(size_t)i1 * D + t]);
    }
    if (i < e) a0 += __ldg(&msg[(size_t)__ldg(&g_elist[i]) * D + t]);
    g_recv[(size_t)n * D + t] = a0 + a1;
}

// ---------------------------------------------------------------------------
// GRU cell (verified scalar path; reads g_recv)
#define GN 16
__global__ __launch_bounds__(256) void gru_kernel(
    const float* __restrict__ nodes, const float* __restrict__ Wi,
    const float* __restrict__ bi, const float* __restrict__ Wh,
    const float* __restrict__ bhn, float* __restrict__ out, int N_)
{
    __shared__ float sR[GN][D];
    __shared__ float sH[GN][D];

    const int t  = threadIdx.x;
    const int n0 = blockIdx.x * GN;

    #pragma unroll
    for (int i = 0; i < (GN * D) / 256; ++i) {
        int idx = t + i * 256;
        int r = idx >> 7, cc = idx & 127;
        int node = min(n0 + r, N_ - 1);
        sR[r][cc] = g_recv[(size_t)node * D + cc];
        sH[r][cc] = nodes[(size_t)node * D + cc];
    }
    __syncthreads();

    const int tx = t & 31;
    const int ty = t >> 5;
    const int r0 = ty * 2, r1 = ty * 2 + 1;
    const int col = tx * 4;

    float aR[2][4], aZ[2][4], aIN[2][4], aHN[2][4];
    #pragma unroll
    for (int i = 0; i < 2; ++i)
        #pragma unroll
        for (int j = 0; j < 4; ++j) { aR[i][j]=0.f; aZ[i][j]=0.f; aIN[i][j]=0.f; aHN[i][j]=0.f; }

    #pragma unroll 4
    for (int k = 0; k < D; ++k) {
        float4 wr = *(const float4*)&Wi[(size_t)k * 3 * D + col];
        float4 wz = *(const float4*)&Wi[(size_t)k * 3 * D + D + col];
        float4 wn = *(const float4*)&Wi[(size_t)k * 3 * D + 2 * D + col];
        float a0 = sR[r0][k], a1 = sR[r1][k];
        aR[0][0]=fmaf(a0,wr.x,aR[0][0]); aR[0][1]=fmaf(a0,wr.y,aR[0][1]); aR[0][2]=fmaf(a0,wr.z,aR[0][2]); aR[0][3]=fmaf(a0,wr.w,aR[0][3]);
        aR[1][0]=fmaf(a1,wr.x,aR[1][0]); aR[1][1]=fmaf(a1,wr.y,aR[1][1]); aR[1][2]=fmaf(a1,wr.z,aR[1][2]); aR[1][3]=fmaf(a1,wr.w,aR[1][3]);
        aZ[0][0]=fmaf(a0,wz.x,aZ[0][0]); aZ[0][1]=fmaf(a0,wz.y,aZ[0][1]); aZ[0][2]=fmaf(a0,wz.z,aZ[0][2]); aZ[0][3]=fmaf(a0,wz.w,aZ[0][3]);
        aZ[1][0]=fmaf(a1,wz.x,aZ[1][0]); aZ[1][1]=fmaf(a1,wz.y,aZ[1][1]); aZ[1][2]=fmaf(a1,wz.z,aZ[1][2]); aZ[1][3]=fmaf(a1,wz.w,aZ[1][3]);
        aIN[0][0]=fmaf(a0,wn.x,aIN[0][0]); aIN[0][1]=fmaf(a0,wn.y,aIN[0][1]); aIN[0][2]=fmaf(a0,wn.z,aIN[0][2]); aIN[0][3]=fmaf(a0,wn.w,aIN[0][3]);
        aIN[1][0]=fmaf(a1,wn.x,aIN[1][0]); aIN[1][1]=fmaf(a1,wn.y,aIN[1][1]); aIN[1][2]=fmaf(a1,wn.z,aIN[1][2]); aIN[1][3]=fmaf(a1,wn.w,aIN[1][3]);
    }
    #pragma unroll 4
    for (int k = 0; k < D; ++k) {
        float4 wr = *(const float4*)&Wh[(size_t)k * 3 * D + col];
        float4 wz = *(const float4*)&Wh[(size_t)k * 3 * D + D + col];
        float4 wn = *(const float4*)&Wh[(size_t)k * 3 * D + 2 * D + col];
        float a0 = sH[r0][k], a1 = sH[r1][k];
        aR[0][0]=fmaf(a0,wr.x,aR[0][0]); aR[0][1]=fmaf(a0,wr.y,aR[0][1]); aR[0][2]=fmaf(a0,wr.z,aR[0][2]); aR[0][3]=fmaf(a0,wr.w,aR[0][3]);
        aR[1][0]=fmaf(a1,wr.x,aR[1][0]); aR[1][1]=fmaf(a1,wr.y,aR[1][1]); aR[1][2]=fmaf(a1,wr.z,aR[1][2]); aR[1][3]=fmaf(a1,wr.w,aR[1][3]);
        aZ[0][0]=fmaf(a0,wz.x,aZ[0][0]); aZ[0][1]=fmaf(a0,wz.y,aZ[0][1]); aZ[0][2]=fmaf(a0,wz.z,aZ[0][2]); aZ[0][3]=fmaf(a0,wz.w,aZ[0][3]);
        aZ[1][0]=fmaf(a1,wz.x,aZ[1][0]); aZ[1][1]=fmaf(a1,wz.y,aZ[1][1]); aZ[1][2]=fmaf(a1,wz.z,aZ[1][2]); aZ[1][3]=fmaf(a1,wz.w,aZ[1][3]);
        aHN[0][0]=fmaf(a0,wn.x,aHN[0][0]); aHN[0][1]=fmaf(a0,wn.y,aHN[0][1]); aHN[0][2]=fmaf(a0,wn.z,aHN[0][2]); aHN[0][3]=fmaf(a0,wn.w,aHN[0][3]);
        aHN[1][0]=fmaf(a1,wn.x,aHN[1][0]); aHN[1][1]=fmaf(a1,wn.y,aHN[1][1]); aHN[1][2]=fmaf(a1,wn.z,aHN[1][2]); aHN[1][3]=fmaf(a1,wn.w,aHN[1][3]);
    }

    float4 br = *(const float4*)&bi[col];
    float4 bz = *(const float4*)&bi[D + col];
    float4 bn = *(const float4*)&bi[2 * D + col];
    float4 bh = *(const float4*)&bhn[col];
    const float brv[4] = {br.x, br.y, br.z, br.w};
    const float bzv[4] = {bz.x, bz.y, bz.z, bz.w};
    const float bnv[4] = {bn.x, bn.y, bn.z, bn.w};
    const float bhv[4] = {bh.x, bh.y, bh.z, bh.w};

    #pragma unroll
    for (int rr = 0; rr < 2; ++rr) {
        int r = ty * 2 + rr;
        int node = n0 + r;
        if (node >= N_) break;
        float o[4];
        #pragma unroll
        for (int j = 0; j < 4; ++j) {
            float rg = 1.f / (1.f + expf(-(aR[rr][j] + brv[j])));
            float zg = 1.f / (1.f + expf(-(aZ[rr][j] + bzv[j])));
            float ng = tanhf(aIN[rr][j] + bnv[j] + rg * (aHN[rr][j] + bhv[j]));
            float h  = sH[r][col + j];
            o[j] = (1.f - zg) * ng + zg * h;
        }
        *(float4*)&out[(size_t)node * D + col] = make_float4(o[0], o[1], o[2], o[3]);
    }
}

// ---------------------------------------------------------------------------
extern "C" void kernel_launch(void* const* d_in, const int* in_sizes, int n_in,
                              void* d_out, int out_size)
{
    const float* nodes  = (const float*)d_in[0];
    const float* edges  = (const float*)d_in[1];
    const float* W_edge = (const float*)d_in[2];
    const float* b_edge = (const float*)d_in[3];
    const float* Wi     = (const float*)d_in[4];
    const float* bi     = (const float*)d_in[5];
    const float* Wh     = (const float*)d_in[6];
    const float* bh_n   = (const float*)d_in[7];
    const int*   snd    = (const int*)d_in[8];
    const int*   rcv    = (const int*)d_in[9];

    const int N_ = in_sizes[0] / D;
    const int E_ = in_sizes[8];

    float* new_nodes = (float*)d_out;
    float* messages  = (float*)d_out + (size_t)N_ * D;

    cudaFuncSetAttribute(edge_mma_kernel,
                         cudaFuncAttributeMaxDynamicSharedMemorySize, SM_EDGE_TOTAL);

    prep_kernel<<<48, 256>>>(W_edge, N_);
    hist_kernel<<<(E_ + 255) / 256, 256>>>(rcv, E_);
    scan_kernel<<<1, 1024>>>(N_, E_);
    scatter_kernel<<<(E_ + 255) / 256, 256>>>(rcv, E_);
    edge_mma_kernel<<<(E_ + 255) / 256, 512, SM_EDGE_TOTAL>>>(
        nodes, edges, b_edge, snd, rcv, messages, E_);
    aggregate_kernel<<<N_, 128>>>(messages, N_);
    gru_kernel<<<(N_ + GN - 1) / GN, 256>>>(nodes, Wi, bi, Wh, bh_n, new_nodes, N_);
}

// round 4
// speedup vs baseline: 2.2828x; 1.3143x over previous
#include <cuda_runtime.h>
#include <cuda_bf16.h>
#include <cstdint>
#include <math.h>

#define D      128
#define N_MAX  20000
#define E_MAX  640000

// ---------------- device scratch (no allocs allowed) ----------------
__device__ float g_recv[(size_t)N_MAX * D];
__device__ float g_P1[(size_t)N_MAX * D];    // nodes @ W[0:128]
__device__ float g_P2[(size_t)N_MAX * D];    // nodes @ W[128:256]
// W_edge pre-split into bf16 hi/lo, mma fragment order:
// index ((c*8 + s)*16 + j)*32 + lane -> uint2
__device__ uint2 g_Bh[3 * 8 * 16 * 32];
__device__ uint2 g_Bl[3 * 8 * 16 * 32];
__device__ int   g_count[N_MAX];
__device__ int   g_off[N_MAX + 1];
__device__ int   g_cursor[N_MAX];
__device__ int   g_elist[E_MAX];

__device__ __forceinline__ uint32_t pack_bf2(float a, float b) {
    __nv_bfloat162 h = __floats2bfloat162_rn(a, b);
    return *(uint32_t*)&h;
}

#define MMA_BF16(d, a0, a1, a2, a3, b0, b1)                                    \
    asm volatile("mma.sync.aligned.m16n8k16.row.col.f32.bf16.bf16.f32 "        \
                 "{%0,%1,%2,%3}, {%4,%5,%6,%7}, {%8,%9}, {%0,%1,%2,%3};"       \
                 : "+f"((d)[0]), "+f"((d)[1]), "+f"((d)[2]), "+f"((d)[3])      \
                 : "r"(a0), "r"(a1), "r"(a2), "r"(a3), "r"(b0), "r"(b1))

// ---------------- shared tile layout (both mma kernels) ----------------
#define A_PITCH 272            // 128 bf16 = 256B + 16B pad
#define SM_BH   0
#define SM_BL   32768
#define SM_AH   65536
#define SM_AL   (65536 + 256 * A_PITCH)
#define SM_TILE_TOTAL (65536 + 2 * 256 * A_PITCH)

// Stage one 256-row x 128-col fp32 source into hi/lo bf16 A tiles.
// Each thread: row = t>>1, half hf = t&1 (64 floats).
__device__ __forceinline__ void stage_A(char* sm, const float* src, int row, int hf) {
    char* awh = sm + SM_AH + row * A_PITCH + hf * 128;
    char* awl = sm + SM_AL + row * A_PITCH + hf * 128;
    #pragma unroll
    for (int q = 0; q < 8; ++q) {
        float4 v0 = __ldg((const float4*)(src + q * 8));
        float4 v1 = __ldg((const float4*)(src + q * 8 + 4));
        float h0 = __bfloat162float(__float2bfloat16_rn(v0.x));
        float h1 = __bfloat162float(__float2bfloat16_rn(v0.y));
        float h2 = __bfloat162float(__float2bfloat16_rn(v0.z));
        float h3 = __bfloat162float(__float2bfloat16_rn(v0.w));
        float h4 = __bfloat162float(__float2bfloat16_rn(v1.x));
        float h5 = __bfloat162float(__float2bfloat16_rn(v1.y));
        float h6 = __bfloat162float(__float2bfloat16_rn(v1.z));
        float h7 = __bfloat162float(__float2bfloat16_rn(v1.w));
        *(uint4*)(awh + q * 16) = make_uint4(pack_bf2(h0, h1), pack_bf2(h2, h3),
                                             pack_bf2(h4, h5), pack_bf2(h6, h7));
        *(uint4*)(awl + q * 16) = make_uint4(pack_bf2(v0.x - h0, v0.y - h1),
                                             pack_bf2(v0.z - h2, v0.w - h3),
                                             pack_bf2(v1.x - h4, v1.y - h5),
                                             pack_bf2(v1.z - h6, v1.w - h7));
    }
}

__device__ __forceinline__ void stage_B(char* sm, int c, int t) {
    const uint4* gbh = (const uint4*)g_Bh + (size_t)c * 2048;
    const uint4* gbl = (const uint4*)g_Bl + (size_t)c * 2048;
    #pragma unroll
    for (int q = 0; q < 4; ++q) {
        int i = t + q * 512;
        *(uint4*)(sm + SM_BH + i * 16) = __ldg(&gbh[i]);
        *(uint4*)(sm + SM_BL + i * 16) = __ldg(&gbl[i]);
    }
}

// 256x128x128 tile compute: 8 k-steps x 16 n-tiles x 3 mma (bf16x3 split)
__device__ __forceinline__ void mma_tile(char* sm, int warp, int lane, float acc[16][4]) {
    const int rA = warp * 16 + (lane >> 2);
    char* aHip = sm + SM_AH + rA * A_PITCH + (lane & 3) * 4;
    char* aLop = sm + SM_AL + rA * A_PITCH + (lane & 3) * 4;
    char* bHip = sm + SM_BH + lane * 8;
    char* bLop = sm + SM_BL + lane * 8;
    #pragma unroll
    for (int s = 0; s < 8; ++s) {
        uint32_t ah0 = *(const uint32_t*)(aHip + s * 32);
        uint32_t ah1 = *(const uint32_t*)(aHip + s * 32 + 8 * A_PITCH);
        uint32_t ah2 = *(const uint32_t*)(aHip + s * 32 + 16);
        uint32_t ah3 = *(const uint32_t*)(aHip + s * 32 + 8 * A_PITCH + 16);
        uint32_t al0 = *(const uint32_t*)(aLop + s * 32);
        uint32_t al1 = *(const uint32_t*)(aLop + s * 32 + 8 * A_PITCH);
        uint32_t al2 = *(const uint32_t*)(aLop + s * 32 + 16);
        uint32_t al3 = *(const uint32_t*)(aLop + s * 32 + 8 * A_PITCH + 16);
        #pragma unroll
        for (int j = 0; j < 16; ++j) {
            uint2 bh = *(const uint2*)(bHip + s * 4096 + j * 256);
            uint2 bl = *(const uint2*)(bLop + s * 4096 + j * 256);
            MMA_BF16(acc[j], ah0, ah1, ah2, ah3, bh.x, bh.y);
            MMA_BF16(acc[j], ah0, ah1, ah2, ah3, bl.x, bl.y);
            MMA_BF16(acc[j], al0, al1, al2, al3, bh.x, bh.y);
        }
    }
}

// ---------------------------------------------------------------------------
// Prep: zero histogram; split W_edge (bf16 hi/lo) into mma-fragment order.
__global__ void prep_kernel(const float* __restrict__ W, int N_) {
    const int stride = gridDim.x * blockDim.x;
    const int TOT = 3 * 8 * 16 * 32;
    for (int i = blockIdx.x * blockDim.x + threadIdx.x; i < TOT; i += stride) {
        int l = i & 31, j = (i >> 5) & 15, s = (i >> 9) & 7, c = i >> 12;
        int k = c * 128 + s * 16 + (l & 3) * 2;
        int n = j * 8 + (l >> 2);
        float w00 = W[(size_t)(k + 0) * D + n];
        float w01 = W[(size_t)(k + 1) * D + n];
        float w10 = W[(size_t)(k + 8) * D + n];
        float w11 = W[(size_t)(k + 9) * D + n];
        float h00 = __bfloat162float(__float2bfloat16_rn(w00));
        float h01 = __bfloat162float(__float2bfloat16_rn(w01));
        float h10 = __bfloat162float(__float2bfloat16_rn(w10));
        float h11 = __bfloat162float(__float2bfloat16_rn(w11));
        g_Bh[i] = make_uint2(pack_bf2(h00, h01), pack_bf2(h10, h11));
        g_Bl[i] = make_uint2(pack_bf2(w00 - h00, w01 - h01),
                             pack_bf2(w10 - h10, w11 - h11));
    }
    for (int i = blockIdx.x * blockDim.x + threadIdx.x; i < N_; i += stride)
        g_count[i] = 0;
}

__global__ void hist_kernel(const int* __restrict__ rcv, int E_) {
    int i = blockIdx.x * blockDim.x + threadIdx.x;
    if (i < E_) atomicAdd(&g_count[rcv[i]], 1);
}

__global__ void scan_kernel(int N_, int E_) {
    __shared__ int part[1024];
    const int t = threadIdx.x;
    const int chunk = (N_ + 1023) >> 10;
    const int lo = t * chunk, hi = min(N_, lo + chunk);
    int s = 0;
    for (int i = lo; i < hi; ++i) s += g_count[i];
    part[t] = s;
    __syncthreads();
    // Hillis-Steele inclusive scan over 1024 partials
    #pragma unroll
    for (int off = 1; off < 1024; off <<= 1) {
        int v = (t >= off) ? part[t - off] : 0;
        __syncthreads();
        part[t] += v;
        __syncthreads();
    }
    int run = part[t] - s;   // exclusive prefix for this thread's chunk
    for (int i = lo; i < hi; ++i) {
        g_off[i] = run; g_cursor[i] = run;
        run += g_count[i];
    }
    if (t == 0) g_off[N_] = E_;
}

__global__ void scatter_kernel(const int* __restrict__ rcv, int E_) {
    int i = blockIdx.x * blockDim.x + threadIdx.x;
    if (i < E_) {
        int p = atomicAdd(&g_cursor[rcv[i]], 1);
        g_elist[p] = i;
    }
}

// ---------------------------------------------------------------------------
// Node projections: P1 = nodes @ W[0:128], P2 = nodes @ W[128:256]
__global__ __launch_bounds__(512, 1) void node_proj_kernel(
    const float* __restrict__ nodes, int N_)
{
    extern __shared__ __align__(16) char sm[];
    const int t    = threadIdx.x;
    const int warp = t >> 5, lane = t & 31;
    const int n0   = blockIdx.x * 256;

    const int row = t >> 1, hf = t & 1;
    const int ng = min(n0 + row, N_ - 1);
    stage_A(sm, nodes + (size_t)ng * D + hf * 64, row, hf);

    const int nr0 = n0 + warp * 16 + (lane >> 2);
    const int nr1 = nr0 + 8;
    const int cb  = (lane & 3) * 2;

    #pragma unroll
    for (int c = 0; c < 2; ++c) {
        if (c) __syncthreads();               // protect B buffer reuse
        stage_B(sm, c, t);
        __syncthreads();

        float acc[16][4];
        #pragma unroll
        for (int j = 0; j < 16; ++j)
            #pragma unroll
            for (int q = 0; q < 4; ++q) acc[j][q] = 0.f;

        mma_tile(sm, warp, lane, acc);

        float* P = c == 0 ? g_P1 : g_P2;
        #pragma unroll
        for (int j = 0; j < 16; ++j) {
            int col = j * 8 + cb;
            if (nr0 < N_) *(float2*)(P + (size_t)nr0 * D + col) = make_float2(acc[j][0], acc[j][1]);
            if (nr1 < N_) *(float2*)(P + (size_t)nr1 * D + col) = make_float2(acc[j][2], acc[j][3]);
        }
    }
}

// ---------------------------------------------------------------------------
// Edge kernel: messages = relu(edges@W3 + P1[snd] + P2[rcv] + b)
__global__ __launch_bounds__(512, 1) void edge_mma_kernel(
    const float* __restrict__ edges, const float* __restrict__ bvec,
    const int* __restrict__ snd, const int* __restrict__ rcv,
    float* __restrict__ msg, int E_)
{
    extern __shared__ __align__(16) char sm[];
    __shared__ float s_bias[128];

    const int t    = threadIdx.x;
    const int warp = t >> 5, lane = t & 31;
    const int e0   = blockIdx.x * 256;

    if (t < 128) s_bias[t] = bvec[t];

    const int row = t >> 1, hf = t & 1;
    const int eg = min(e0 + row, E_ - 1);
    stage_A(sm, edges + (size_t)eg * D + hf * 64, row, hf);
    stage_B(sm, 2, t);
    __syncthreads();

    float acc[16][4];
    #pragma unroll
    for (int j = 0; j < 16; ++j)
        #pragma unroll
        for (int q = 0; q < 4; ++q) acc[j][q] = 0.f;

    mma_tile(sm, warp, lane, acc);

    // epilogue: gather node projections, add bias, relu, store
    const int er0 = e0 + warp * 16 + (lane >> 2);
    const int cb  = (lane & 3) * 2;
    #pragma unroll
    for (int rr = 0; rr < 2; ++rr) {
        int er = er0 + rr * 8;
        if (er < E_) {
            int sn = __ldg(&snd[er]);
            int rc = __ldg(&rcv[er]);
            const float* p1 = g_P1 + (size_t)sn * D;
            const float* p2 = g_P2 + (size_t)rc * D;
            float* mp = msg + (size_t)er * D;
            #pragma unroll
            for (int j = 0; j < 16; ++j) {
                int col = j * 8 + cb;
                float2 q1 = *(const float2*)(p1 + col);
                float2 q2 = *(const float2*)(p2 + col);
                float2 o;
                o.x = fmaxf(acc[j][rr * 2 + 0] + q1.x + q2.x + s_bias[col], 0.f);
                o.y = fmaxf(acc[j][rr * 2 + 1] + q1.y + q2.y + s_bias[col + 1], 0.f);
                *(float2*)(mp + col) = o;
            }
        }
    }
}

// ---------------------------------------------------------------------------
// CSR gather-reduce: g_recv[n,:] = sum_{e: rcv[e]==n} messages[e,:]
__global__ __launch_bounds__(128) void aggregate_kernel(const float* __restrict__ msg, int N_) {
    const int n = blockIdx.x;
    const int t = threadIdx.x;
    const int s = g_off[n], e = g_off[n + 1];
    float a0 = 0.f, a1 = 0.f;
    int i = s;
    for (; i + 2 <= e; i += 2) {
        int i0 = __ldg(&g_elist[i]);
        int i1 = __ldg(&g_elist[i + 1]);
        a0 += __ldg(&msg[(size_t)i0 * D + t]);
        a1 += __ldg(&msg[(size_t)i1 * D + t]);
    }
    if (i < e) a0 += __ldg(&msg[(size_t)__ldg(&g_elist[i]) * D + t]);
    g_recv[(size_t)n * D + t] = a0 + a1;
}

// ---------------------------------------------------------------------------
// GRU cell (verified scalar path; reads g_recv)
#define GN 16
__global__ __launch_bounds__(256) void gru_kernel(
    const float* __restrict__ nodes, const float* __restrict__ Wi,
    const float* __restrict__ bi, const float* __restrict__ Wh,
    const float* __restrict__ bhn, float* __restrict__ out, int N_)
{
    __shared__ float sR[GN][D];
    __shared__ float sH[GN][D];

    const int t  = threadIdx.x;
    const int n0 = blockIdx.x * GN;

    #pragma unroll
    for (int i = 0; i < (GN * D) / 256; ++i) {
        int idx = t + i * 256;
        int r = idx >> 7, cc = idx & 127;
        int node = min(n0 + r, N_ - 1);
        sR[r][cc] = g_recv[(size_t)node * D + cc];
        sH[r][cc] = nodes[(size_t)node * D + cc];
    }
    __syncthreads();

    const int tx = t & 31;
    const int ty = t >> 5;
    const int r0 = ty * 2, r1 = ty * 2 + 1;
    const int col = tx * 4;

    float aR[2][4], aZ[2][4], aIN[2][4], aHN[2][4];
    #pragma unroll
    for (int i = 0; i < 2; ++i)
        #pragma unroll
        for (int j = 0; j < 4; ++j) { aR[i][j]=0.f; aZ[i][j]=0.f; aIN[i][j]=0.f; aHN[i][j]=0.f; }

    #pragma unroll 4
    for (int k = 0; k < D; ++k) {
        float4 wr = *(const float4*)&Wi[(size_t)k * 3 * D + col];
        float4 wz = *(const float4*)&Wi[(size_t)k * 3 * D + D + col];
        float4 wn = *(const float4*)&Wi[(size_t)k * 3 * D + 2 * D + col];
        float a0 = sR[r0][k], a1 = sR[r1][k];
        aR[0][0]=fmaf(a0,wr.x,aR[0][0]); aR[0][1]=fmaf(a0,wr.y,aR[0][1]); aR[0][2]=fmaf(a0,wr.z,aR[0][2]); aR[0][3]=fmaf(a0,wr.w,aR[0][3]);
        aR[1][0]=fmaf(a1,wr.x,aR[1][0]); aR[1][1]=fmaf(a1,wr.y,aR[1][1]); aR[1][2]=fmaf(a1,wr.z,aR[1][2]); aR[1][3]=fmaf(a1,wr.w,aR[1][3]);
        aZ[0][0]=fmaf(a0,wz.x,aZ[0][0]); aZ[0][1]=fmaf(a0,wz.y,aZ[0][1]); aZ[0][2]=fmaf(a0,wz.z,aZ[0][2]); aZ[0][3]=fmaf(a0,wz.w,aZ[0][3]);
        aZ[1][0]=fmaf(a1,wz.x,aZ[1][0]); aZ[1][1]=fmaf(a1,wz.y,aZ[1][1]); aZ[1][2]=fmaf(a1,wz.z,aZ[1][2]); aZ[1][3]=fmaf(a1,wz.w,aZ[1][3]);
        aIN[0][0]=fmaf(a0,wn.x,aIN[0][0]); aIN[0][1]=fmaf(a0,wn.y,aIN[0][1]); aIN[0][2]=fmaf(a0,wn.z,aIN[0][2]); aIN[0][3]=fmaf(a0,wn.w,aIN[0][3]);
        aIN[1][0]=fmaf(a1,wn.x,aIN[1][0]); aIN[1][1]=fmaf(a1,wn.y,aIN[1][1]); aIN[1][2]=fmaf(a1,wn.z,aIN[1][2]); aIN[1][3]=fmaf(a1,wn.w,aIN[1][3]);
    }
    #pragma unroll 4
    for (int k = 0; k < D; ++k) {
        float4 wr = *(const float4*)&Wh[(size_t)k * 3 * D + col];
        float4 wz = *(const float4*)&Wh[(size_t)k * 3 * D + D + col];
        float4 wn = *(const float4*)&Wh[(size_t)k * 3 * D + 2 * D + col];
        float a0 = sH[r0][k], a1 = sH[r1][k];
        aR[0][0]=fmaf(a0,wr.x,aR[0][0]); aR[0][1]=fmaf(a0,wr.y,aR[0][1]); aR[0][2]=fmaf(a0,wr.z,aR[0][2]); aR[0][3]=fmaf(a0,wr.w,aR[0][3]);
        aR[1][0]=fmaf(a1,wr.x,aR[1][0]); aR[1][1]=fmaf(a1,wr.y,aR[1][1]); aR[1][2]=fmaf(a1,wr.z,aR[1][2]); aR[1][3]=fmaf(a1,wr.w,aR[1][3]);
        aZ[0][0]=fmaf(a0,wz.x,aZ[0][0]); aZ[0][1]=fmaf(a0,wz.y,aZ[0][1]); aZ[0][2]=fmaf(a0,wz.z,aZ[0][2]); aZ[0][3]=fmaf(a0,wz.w,aZ[0][3]);
        aZ[1][0]=fmaf(a1,wz.x,aZ[1][0]); aZ[1][1]=fmaf(a1,wz.y,aZ[1][1]); aZ[1][2]=fmaf(a1,wz.z,aZ[1][2]); aZ[1][3]=fmaf(a1,wz.w,aZ[1][3]);
        aHN[0][0]=fmaf(a0,wn.x,aHN[0][0]); aHN[0][1]=fmaf(a0,wn.y,aHN[0][1]); aHN[0][2]=fmaf(a0,wn.z,aHN[0][2]); aHN[0][3]=fmaf(a0,wn.w,aHN[0][3]);
        aHN[1][0]=fmaf(a1,wn.x,aHN[1][0]); aHN[1][1]=fmaf(a1,wn.y,aHN[1][1]); aHN[1][2]=fmaf(a1,wn.z,aHN[1][2]); aHN[1][3]=fmaf(a1,wn.w,aHN[1][3]);
    }

    float4 br = *(const float4*)&bi[col];
    float4 bz = *(const float4*)&bi[D + col];
    float4 bn = *(const float4*)&bi[2 * D + col];
    float4 bh = *(const float4*)&bhn[col];
    const float brv[4] = {br.x, br.y, br.z, br.w};
    const float bzv[4] = {bz.x, bz.y, bz.z, bz.w};
    const float bnv[4] = {bn.x, bn.y, bn.z, bn.w};
    const float bhv[4] = {bh.x, bh.y, bh.z, bh.w};

    #pragma unroll
    for (int rr = 0; rr < 2; ++rr) {
        int r = ty * 2 + rr;
        int node = n0 + r;
        if (node >= N_) break;
        float o[4];
        #pragma unroll
        for (int j = 0; j < 4; ++j) {
            float rg = 1.f / (1.f + expf(-(aR[rr][j] + brv[j])));
            float zg = 1.f / (1.f + expf(-(aZ[rr][j] + bzv[j])));
            float ng = tanhf(aIN[rr][j] + bnv[j] + rg * (aHN[rr][j] + bhv[j]));
            float h  = sH[r][col + j];
            o[j] = (1.f - zg) * ng + zg * h;
        }
        *(float4*)&out[(size_t)node * D + col] = make_float4(o[0], o[1], o[2], o[3]);
    }
}

// ---------------------------------------------------------------------------
extern "C" void kernel_launch(void* const* d_in, const int* in_sizes, int n_in,
                              void* d_out, int out_size)
{
    const float* nodes  = (const float*)d_in[0];
    const float* edges  = (const float*)d_in[1];
    const float* W_edge = (const float*)d_in[2];
    const float* b_edge = (const float*)d_in[3];
    const float* Wi     = (const float*)d_in[4];
    const float* bi     = (const float*)d_in[5];
    const float* Wh     = (const float*)d_in[6];
    const float* bh_n   = (const float*)d_in[7];
    const int*   snd    = (const int*)d_in[8];
    const int*   rcv    = (const int*)d_in[9];

    const int N_ = in_sizes[0] / D;
    const int E_ = in_sizes[8];

    float* new_nodes = (float*)d_out;
    float* messages  = (float*)d_out + (size_t)N_ * D;

    cudaFuncSetAttribute(node_proj_kernel,
                         cudaFuncAttributeMaxDynamicSharedMemorySize, SM_TILE_TOTAL);
    cudaFuncSetAttribute(edge_mma_kernel,
                         cudaFuncAttributeMaxDynamicSharedMemorySize, SM_TILE_TOTAL);

    prep_kernel<<<48, 256>>>(W_edge, N_);
    hist_kernel<<<(E_ + 255) / 256, 256>>>(rcv, E_);
    scan_kernel<<<1, 1024>>>(N_, E_);
    scatter_kernel<<<(E_ + 255) / 256, 256>>>(rcv, E_);
    node_proj_kernel<<<(N_ + 255) / 256, 512, SM_TILE_TOTAL>>>(nodes, N_);
    edge_mma_kernel<<<(E_ + 255) / 256, 512, SM_TILE_TOTAL>>>(
        edges, b_edge, snd, rcv, messages, E_);
    aggregate_kernel<<<N_, 128>>>(messages, N_);
    gru_kernel<<<(N_ + GN - 1) / GN, 256>>>(nodes, Wi, bi, Wh, bh_n, new_nodes, N_);
}